// round 16
// baseline (speedup 1.0000x reference)
#include <cuda_runtime.h>
#include <cstdint>

#define BS   2
#define NH   16
#define NB1  9
#define ML   1024
#define NI   64
#define N2V  1088
#define DM   1024
#define DK   64
#define TOPK 16
#define KPAD 258

typedef unsigned long long ull;

// ---------------- f32x2 packed helpers (each lane = independent IEEE fp32 op) ----
__device__ __forceinline__ ull pk2(float lo, float hi) {
    ull r; asm("mov.b64 %0,{%1,%2};" : "=l"(r) : "f"(lo), "f"(hi)); return r;
}
__device__ __forceinline__ float2 upk2(ull a) {
    float2 f; asm("mov.b64 {%0,%1},%2;" : "=f"(f.x), "=f"(f.y) : "l"(a)); return f;
}
__device__ __forceinline__ ull fma2(ull a, ull b, ull c) {
    ull d; asm("fma.rn.f32x2 %0,%1,%2,%3;" : "=l"(d) : "l"(a), "l"(b), "l"(c)); return d;
}
__device__ __forceinline__ ull add2(ull a, ull b) {
    ull d; asm("add.rn.f32x2 %0,%1,%2;" : "=l"(d) : "l"(a), "l"(b)); return d;
}
__device__ __forceinline__ ull neg2(ull a) { return a ^ 0x8000000080000000ULL; }

// packed Kahan fold: acc += part with compensation (exact match of scalar version)
__device__ __forceinline__ void kahan2(ull& acc, ull& cmp, ull part) {
    ull y  = add2(part, neg2(cmp));
    ull t2 = add2(acc, y);
    cmp = add2(add2(t2, neg2(acc)), neg2(y));
    acc = t2;
}

// order-preserving fp32 <-> u32 bijection (no NaNs in this data)
__device__ __forceinline__ unsigned xf(float v) {
    unsigned b = __float_as_uint(v);
    return (b & 0x80000000u) ? ~b : (b | 0x80000000u);
}
__device__ __forceinline__ float ixf(unsigned u) {
    unsigned b = (u & 0x80000000u) ? (u & 0x7fffffffu) : ~u;
    return __uint_as_float(b);
}

// ---------------- device scratch ----------------
__device__ float g_q[BS*NH*ML*DK];
__device__ float g_k[BS*NH*N2V*DK];
__device__ float g_v[BS*NH*N2V*DK];
__device__ int   g_rows_q[BS*NB1*ML];
__device__ int   g_rows_kv[BS*NB1*N2V];
__device__ int   g_cnt_q[BS*NB1];
__device__ int   g_cnt_kv[BS*NB1];

// ---------------- group building ----------------
__global__ void zero_counts_kernel() {
    int t = threadIdx.x;
    if (t < BS*NB1) { g_cnt_q[t] = 0; g_cnt_kv[t] = 0; }
}

__global__ void build_groups_kernel(const int* __restrict__ b_seq,
                                    const int* __restrict__ b_seq2) {
    int t = blockIdx.x * blockDim.x + threadIdx.x;
    if (t < BS*ML) {
        int b = t / ML;
        int B = b_seq[t];
        int pos = atomicAdd(&g_cnt_q[b*NB1 + B], 1);
        g_rows_q[(b*NB1 + B)*ML + pos] = t % ML;
    } else if (t < BS*ML + BS*N2V) {
        int u = t - BS*ML;
        int b = u / N2V;
        int B = b_seq2[u];
        int pos = atomicAdd(&g_cnt_kv[b*NB1 + B], 1);
        g_rows_kv[(b*NB1 + B)*N2V + pos] = u % N2V;
    }
}

// ---------------- cp.async helpers ----------------
__device__ __forceinline__ void cp_async16(uint32_t smem_addr, const void* gptr) {
    asm volatile("cp.async.ca.shared.global [%0], [%1], 16;\n"
                 :: "r"(smem_addr), "l"(gptr));
}
__device__ __forceinline__ void cp_async_commit() {
    asm volatile("cp.async.commit_group;\n");
}
__device__ __forceinline__ void cp_async_wait0() {
    asm volatile("cp.async.wait_group 0;\n");
}

// ---------------- merged grouped projection GEMM (R15 exact) ----------------
#define PBF (32*136)
#define PAF (32*68)
#define PA_OFF (2*PBF)
#define PR_OFF (PA_OFF + 2*PAF)
__global__ __launch_bounds__(256, 2)
void proj_gemm_kernel(const float* __restrict__ item,
                      const float* __restrict__ intent,
                      const float* __restrict__ W_item,
                      const float* __restrict__ W_intent,
                      const int* __restrict__ rows_q, const int* __restrict__ cnt_q,
                      const int* __restrict__ rows_kv, const int* __restrict__ cnt_kv,
                      float* __restrict__ Oq, float* __restrict__ Ok, float* __restrict__ Ov)
{
    extern __shared__ __align__(16) float psm[];
    int*   rows_s = (int*)(psm + PR_OFF);

    int z     = blockIdx.z;
    int which = z >> 1;          // 0=q, 1=k, 2=v
    int b     = z & 1;
    int B     = blockIdx.y;
    int tm    = blockIdx.x % 17;
    int tn    = blockIdx.x / 17;         // 0..7

    const float* X;  const float* W;  const int* rl;  int cnt, Rin;
    float* O;
    if (which == 0) {
        cnt = cnt_q[b*NB1 + B];
        X = item;   W = W_item  + (size_t)B * (DM*DM);
        rl = rows_q  + (size_t)(b*NB1 + B) * ML;   Rin = ML;   O = Oq;
    } else {
        cnt = cnt_kv[b*NB1 + B];
        X = intent; W = W_intent + (size_t)(which-1) * (NB1*DM*DM) + (size_t)B * (DM*DM);
        rl = rows_kv + (size_t)(b*NB1 + B) * N2V;  Rin = N2V;
        O = (which == 1) ? Ok : Ov;
    }
    int Rout = (which == 0) ? ML : N2V;

    int m0 = tm * 64;
    if (m0 >= cnt) return;
    int n0 = tn * 128;

    int t = threadIdx.x;
    if (t < 64) rows_s[t] = (m0 + t < cnt) ? rl[m0 + t] : -1;
    __syncthreads();

    int ai = t >> 2;
    int akq = (t & 3) * 4;
    int aRow = rows_s[ai];
    const float* aSrc = (aRow >= 0) ? &X[((size_t)b * Rin + aRow) * DM + akq] : nullptr;

    int ty = t >> 4;
    int tx = t & 15;

    ull acc2[4][4], cmp2[4][4];
#pragma unroll
    for (int i = 0; i < 4; i++)
#pragma unroll
        for (int j = 0; j < 4; j++) { acc2[i][j] = 0ULL; cmp2[i][j] = 0ULL; }

    uint32_t bBase = (uint32_t)__cvta_generic_to_shared(psm);
    int kk0 = (t + 0)   >> 5, c0 = ((t + 0)   & 31) * 4;
    int kk1 = (t + 256) >> 5, c1 = ((t + 256) & 31) * 4;
    int kk2 = (t + 512) >> 5, c2 = ((t + 512) & 31) * 4;
    int kk3 = (t + 768) >> 5, c3 = ((t + 768) & 31) * 4;

    // ---- prologue: super-chunk 0 ----
    {
        uint32_t bb = bBase;
        cp_async16(bb + (uint32_t)(kk0*136 + c0)*4, &W[(size_t)kk0 * DM + n0 + c0]);
        cp_async16(bb + (uint32_t)(kk1*136 + c1)*4, &W[(size_t)kk1 * DM + n0 + c1]);
        cp_async16(bb + (uint32_t)(kk2*136 + c2)*4, &W[(size_t)kk2 * DM + n0 + c2]);
        cp_async16(bb + (uint32_t)(kk3*136 + c3)*4, &W[(size_t)kk3 * DM + n0 + c3]);
        cp_async_commit();
        float4 av0 = make_float4(0.f,0.f,0.f,0.f), av1 = av0;
        if (aSrc) { av0 = *(const float4*)aSrc; av1 = *(const float4*)(aSrc + 16); }
        float* A0 = psm + PA_OFF;
        A0[(akq+0)*68 + ai] = av0.x; A0[(akq+1)*68 + ai] = av0.y;
        A0[(akq+2)*68 + ai] = av0.z; A0[(akq+3)*68 + ai] = av0.w;
        A0[(akq+16)*68 + ai] = av1.x; A0[(akq+17)*68 + ai] = av1.y;
        A0[(akq+18)*68 + ai] = av1.z; A0[(akq+19)*68 + ai] = av1.w;
        cp_async_wait0();
        __syncthreads();
    }

    const int NSC = DM / 32;
    for (int i = 0; i < NSC; i++) {
        int cur = i & 1, nxt = cur ^ 1;
        float4 av0, av1;
        bool pre = (i + 1 < NSC);
        if (pre) {
            int kp1 = (i + 1) * 32;
            uint32_t bb = bBase + (uint32_t)(nxt * PBF) * 4;
            cp_async16(bb + (uint32_t)(kk0*136 + c0)*4, &W[(size_t)(kp1 + kk0) * DM + n0 + c0]);
            cp_async16(bb + (uint32_t)(kk1*136 + c1)*4, &W[(size_t)(kp1 + kk1) * DM + n0 + c1]);
            cp_async16(bb + (uint32_t)(kk2*136 + c2)*4, &W[(size_t)(kp1 + kk2) * DM + n0 + c2]);
            cp_async16(bb + (uint32_t)(kk3*136 + c3)*4, &W[(size_t)(kp1 + kk3) * DM + n0 + c3]);
            cp_async_commit();
            av0 = make_float4(0.f,0.f,0.f,0.f); av1 = av0;
            if (aSrc) { av0 = *(const float4*)(aSrc + kp1); av1 = *(const float4*)(aSrc + kp1 + 16); }
        }

        const float* Bc = psm + cur * PBF;
        const float* Ac = psm + PA_OFF + cur * PAF;

#pragma unroll
        for (int kh = 0; kh < 2; kh++) {
            ull part2[4][4];
#pragma unroll
            for (int ii = 0; ii < 4; ii++)
#pragma unroll
                for (int j = 0; j < 4; j++) part2[ii][j] = 0ULL;

#pragma unroll
            for (int kq = 0; kq < 16; kq++) {
                int kk = kh*16 + kq;
                float4 a4 = *(const float4*)&Ac[kk*68 + ty*4];
                const ull* bpa = (const ull*)&Bc[kk*136 + tx*4];
                const ull* bpb = (const ull*)&Bc[kk*136 + 64 + tx*4];
                ull b2[4] = { bpa[0], bpa[1], bpb[0], bpb[1] };
                ull a2[4] = { pk2(a4.x, a4.x), pk2(a4.y, a4.y),
                              pk2(a4.z, a4.z), pk2(a4.w, a4.w) };
#pragma unroll
                for (int ii = 0; ii < 4; ii++)
#pragma unroll
                    for (int j = 0; j < 4; j++)
                        part2[ii][j] = fma2(a2[ii], b2[j], part2[ii][j]);
            }
#pragma unroll
            for (int ii = 0; ii < 4; ii++)
#pragma unroll
                for (int j = 0; j < 4; j++)
                    kahan2(acc2[ii][j], cmp2[ii][j], part2[ii][j]);
        }

        if (pre) {
            float* An = psm + PA_OFF + nxt * PAF;
            An[(akq+0)*68 + ai] = av0.x; An[(akq+1)*68 + ai] = av0.y;
            An[(akq+2)*68 + ai] = av0.z; An[(akq+3)*68 + ai] = av0.w;
            An[(akq+16)*68 + ai] = av1.x; An[(akq+17)*68 + ai] = av1.y;
            An[(akq+18)*68 + ai] = av1.z; An[(akq+19)*68 + ai] = av1.w;
            cp_async_wait0();
        }
        __syncthreads();
    }

    // epilogue
#pragma unroll
    for (int i = 0; i < 4; i++) {
        int n = rows_s[ty*4 + i];
        if (n < 0) continue;
#pragma unroll
        for (int jp = 0; jp < 4; jp++) {
            float2 v = upk2(acc2[i][jp]);
            int cbase = n0 + ((jp < 2) ? (tx*4 + jp*2) : (64 + tx*4 + (jp-2)*2));
#pragma unroll
            for (int l = 0; l < 2; l++) {
                int col = cbase + l;
                int h   = col >> 6;
                int kd  = col & 63;
                O[(((size_t)b*NH + h) * Rout + n) * DK + kd] = (l == 0) ? v.x : v.y;
            }
        }
    }
}

// ---------------- fused attention: R15 score loop + REDUX-based selection ---
__global__ __launch_bounds__(256, 2)
void attn_kernel(const float* __restrict__ q, const float* __restrict__ kmat,
                 const float* __restrict__ vmat, float* __restrict__ out)
{
    extern __shared__ __align__(16) float sm[];
    float* q_s = sm;                       // 16*64   = 1024
    float* sc  = sm + 16*DK;               // 16*1088 = 17408
    float* k_s = sc + 16*N2V;              // 32*KPAD = 8256

    int b  = blockIdx.z;
    int h  = blockIdx.y;
    int n0 = blockIdx.x * 16;
    int t  = threadIdx.x;

    {
        const float4* qb = (const float4*)(q + (((size_t)(b*NH + h)) * ML + n0) * DK);
        ((float4*)q_s)[t] = qb[t];
    }

    const float* kb = kmat + ((size_t)(b*NH + h)) * N2V * DK;

    int tm = t & 63;
    int tr = t >> 6;
    int mlb = t >> 3;
    int c4  = (t & 7) * 4;

    for (int mc = 0; mc < N2V; mc += 256) {
        ull acc2[4][2], cmp2[4][2];
#pragma unroll
        for (int i = 0; i < 4; i++)
#pragma unroll
            for (int j = 0; j < 2; j++) { acc2[i][j] = 0ULL; cmp2[i][j] = 0ULL; }

#pragma unroll
        for (int h2 = 0; h2 < 2; h2++) {
            __syncthreads();
#pragma unroll
            for (int r = 0; r < 8; r++) {
                int ml = mlb + r * 32;
                int m  = mc + ml;
                float4 vv = make_float4(0.f, 0.f, 0.f, 0.f);
                if (m < N2V) vv = *(const float4*)(kb + (size_t)m * DK + h2*32 + c4);
                k_s[(c4+0)*KPAD + ml] = vv.x; k_s[(c4+1)*KPAD + ml] = vv.y;
                k_s[(c4+2)*KPAD + ml] = vv.z; k_s[(c4+3)*KPAD + ml] = vv.w;
            }
            __syncthreads();

#pragma unroll
            for (int kh = 0; kh < 2; kh++) {
                int kc = 2*h2 + kh;
                ull part2[4][2];
#pragma unroll
                for (int i = 0; i < 4; i++)
#pragma unroll
                    for (int j = 0; j < 2; j++) part2[i][j] = 0ULL;

#pragma unroll
                for (int kq = 0; kq < 16; kq++) {
                    int kkl = kh*16 + kq;
                    const float* kr = k_s + kkl*KPAD;
                    ull k2a = *(const ull*)(kr + 2*tm);
                    ull k2b = *(const ull*)(kr + 128 + 2*tm);
#pragma unroll
                    for (int rr = 0; rr < 4; rr++) {
                        float qv = q_s[(tr*4 + rr) * DK + kc*16 + kq];
                        ull q2 = pk2(qv, qv);
                        part2[rr][0] = fma2(q2, k2a, part2[rr][0]);
                        part2[rr][1] = fma2(q2, k2b, part2[rr][1]);
                    }
                }
#pragma unroll
                for (int i = 0; i < 4; i++)
#pragma unroll
                    for (int j = 0; j < 2; j++)
                        kahan2(acc2[i][j], cmp2[i][j], part2[i][j]);
            }
        }

#pragma unroll
        for (int p = 0; p < 2; p++) {
            int mbase = mc + p*128 + 2*tm;
            if (mbase >= N2V) continue;
#pragma unroll
            for (int rr = 0; rr < 4; rr++) {
                int row = tr*4 + rr;
                float2 s2 = upk2(acc2[rr][p]);
                s2.x *= 0.125f; s2.y *= 0.125f;
                *(float2*)(sc + row*N2V + mbase) = s2;
            }
        }
    }
    __syncthreads();

    // ---- dual-row interleaved softmax + top-16 + PV (REDUX selection) ----
    int warp = t >> 5, lane = t & 31;
    const float* vb = vmat + ((size_t)(b*NH + h)) * N2V * DK;
    const size_t XSZ = (size_t)BS * ML * NH * DK;

    float* pbuf = k_s;
    int*   ibuf = (int*)(k_s + 16*64);

    int row0 = warp * 2, row1 = row0 + 1;
    int nn0 = n0 + row0, nn1 = n0 + row1;
    float* sr0 = sc + row0 * N2V;
    float* sr1 = sc + row1 * N2V;

    // softmax stats
    float M0 = -3.4e38f, M1 = -3.4e38f;
#pragma unroll
    for (int j = 0; j < 34; j++) {
        M0 = fmaxf(M0, sr0[lane + 32*j]);
        M1 = fmaxf(M1, sr1[lane + 32*j]);
    }
    M0 = ixf(__reduce_max_sync(0xffffffffu, xf(M0)));
    M1 = ixf(__reduce_max_sync(0xffffffffu, xf(M1)));
    float Z0 = 0.f, Z1 = 0.f;
#pragma unroll
    for (int j = 0; j < 34; j++) {
        Z0 += __expf(sr0[lane + 32*j] - M0);
        Z1 += __expf(sr1[lane + 32*j] - M1);
    }
#pragma unroll
    for (int o = 16; o > 0; o >>= 1) {
        Z0 += __shfl_xor_sync(0xffffffffu, Z0, o);
        Z1 += __shfl_xor_sync(0xffffffffu, Z1, o);
    }
    float invZ0 = 1.0f / Z0, invZ1 = 1.0f / Z1;

    // --- selection, segment A: dual per-lane (top1, top2), REDUX argmax ---
    {
        float lbv0 = -3.4e38f, lv20 = -3.4e38f; int lbi0 = lane, li20 = lane; bool need0 = false;
        float lbv1 = -3.4e38f, lv21 = -3.4e38f; int lbi1 = lane, li21 = lane; bool need1 = false;
#pragma unroll
        for (int j = 0; j < 32; j++) {
            int idx = lane + 32*j;
            float s0 = sr0[idx], s1 = sr1[idx];
            if (s0 > lbv0)      { lv20 = lbv0; li20 = lbi0; lbv0 = s0; lbi0 = idx; }
            else if (s0 > lv20) { lv20 = s0;  li20 = idx; }
            if (s1 > lbv1)      { lv21 = lbv1; li21 = lbi1; lbv1 = s1; lbi1 = idx; }
            else if (s1 > lv21) { lv21 = s1;  li21 = idx; }
        }
        unsigned lu0 = xf(lbv0), lu1 = xf(lbv1);
        for (int it = 0; it < TOPK; it++) {
            unsigned mu0 = __reduce_max_sync(0xffffffffu, lu0);
            unsigned mu1 = __reduce_max_sync(0xffffffffu, lu1);
            int bi0 = __reduce_min_sync(0xffffffffu, (lu0 == mu0) ? lbi0 : 0x7fffffff);
            int bi1 = __reduce_min_sync(0xffffffffu, (lu1 == mu1) ? lbi1 : 0x7fffffff);
            float bv0 = ixf(mu0), bv1 = ixf(mu1);
            if ((bi0 & 31) == lane) {
                sr0[bi0] = -3.4e38f;
                if (need0) {
                    lbv0 = -3.4e38f; lv20 = -3.4e38f; lbi0 = lane; li20 = lane;
#pragma unroll
                    for (int j = 0; j < 32; j++) {
                        int idx = lane + 32*j;
                        float s = sr0[idx];
                        if (s > lbv0)      { lv20 = lbv0; li20 = lbi0; lbv0 = s; lbi0 = idx; }
                        else if (s > lv20) { lv20 = s;  li20 = idx; }
                    }
                    need0 = false;
                } else { lbv0 = lv20; lbi0 = li20; need0 = true; }
                lu0 = xf(lbv0);
            }
            if ((bi1 & 31) == lane) {
                sr1[bi1] = -3.4e38f;
                if (need1) {
                    lbv1 = -3.4e38f; lv21 = -3.4e38f; lbi1 = lane; li21 = lane;
#pragma unroll
                    for (int j = 0; j < 32; j++) {
                        int idx = lane + 32*j;
                        float s = sr1[idx];
                        if (s > lbv1)      { lv21 = lbv1; li21 = lbi1; lbv1 = s; lbi1 = idx; }
                        else if (s > lv21) { lv21 = s;  li21 = idx; }
                    }
                    need1 = false;
                } else { lbv1 = lv21; lbi1 = li21; need1 = true; }
                lu1 = xf(lbv1);
            }
            __syncwarp();
            if (lane == 0) {
                pbuf[row0*64 + it] = bv0; ibuf[row0*64 + it] = bi0;
                pbuf[row1*64 + it] = bv1; ibuf[row1*64 + it] = bi1;
                if (h == 0 && it == 0) {
                    out[XSZ + (size_t)b*ML + nn0] = (float)bi0;
                    out[XSZ + (size_t)b*ML + nn1] = (float)bi1;
                }
            }
        }
    }

    // --- selection, segment B: dual, 2 elems/lane, REDUX argmax ---
    {
        float lbv0, lv20, lbv1, lv21;
        int   lbi0, li20, lbi1, li21;
        {
            float s0 = sr0[ML + lane], s1 = sr0[ML + lane + 32];
            if (s0 >= s1) { lbv0 = s0; lbi0 = ML + lane;      lv20 = s1; li20 = ML + lane + 32; }
            else          { lbv0 = s1; lbi0 = ML + lane + 32; lv20 = s0; li20 = ML + lane; }
        }
        {
            float s0 = sr1[ML + lane], s1 = sr1[ML + lane + 32];
            if (s0 >= s1) { lbv1 = s0; lbi1 = ML + lane;      lv21 = s1; li21 = ML + lane + 32; }
            else          { lbv1 = s1; lbi1 = ML + lane + 32; lv21 = s0; li21 = ML + lane; }
        }
        unsigned lu0 = xf(lbv0), lu1 = xf(lbv1);
        for (int it = 0; it < TOPK; it++) {
            unsigned mu0 = __reduce_max_sync(0xffffffffu, lu0);
            unsigned mu1 = __reduce_max_sync(0xffffffffu, lu1);
            int bi0 = __reduce_min_sync(0xffffffffu, (lu0 == mu0) ? lbi0 : 0x7fffffff);
            int bi1 = __reduce_min_sync(0xffffffffu, (lu1 == mu1) ? lbi1 : 0x7fffffff);
            float bv0 = ixf(mu0), bv1 = ixf(mu1);
            if ((bi0 & 31) == lane) { lbv0 = lv20; lbi0 = li20; lv20 = -3.4e38f; lu0 = xf(lbv0); }
            if ((bi1 & 31) == lane) { lbv1 = lv21; lbi1 = li21; lv21 = -3.4e38f; lu1 = xf(lbv1); }
            __syncwarp();
            if (lane == 0) {
                pbuf[row0*64 + 16 + it] = bv0; ibuf[row0*64 + 16 + it] = bi0;
                pbuf[row1*64 + 16 + it] = bv1; ibuf[row1*64 + 16 + it] = bi1;
                if (h == 0 && it == 0) {
                    out[XSZ + (size_t)BS*ML + (size_t)b*ML + nn0] = (float)(bi0 - ML);
                    out[XSZ + (size_t)BS*ML + (size_t)b*ML + nn1] = (float)(bi1 - ML);
                }
            }
        }
    }
    __syncwarp();

    // --- PV, both rows interleaved ---
    float a00 = 0.f, a01 = 0.f, a10 = 0.f, a11 = 0.f;
#pragma unroll 4
    for (int it = 0; it < 32; it++) {
        float bv0 = pbuf[row0*64 + it]; int g0 = ibuf[row0*64 + it];
        float bv1 = pbuf[row1*64 + it]; int g1 = ibuf[row1*64 + it];
        float p0 = __expf(bv0 - M0) * invZ0;
        float p1 = __expf(bv1 - M1) * invZ1;
        const float* v0 = vb + (size_t)g0 * DK;
        const float* v1 = vb + (size_t)g1 * DK;
        a00 += p0 * v0[lane];  a01 += p0 * v0[lane + 32];
        a10 += p1 * v1[lane];  a11 += p1 * v1[lane + 32];
    }

    out[((size_t)b*ML + nn0) * (NH*DK) + h*DK + lane]      = a00;
    out[((size_t)b*ML + nn0) * (NH*DK) + h*DK + lane + 32] = a01;
    out[((size_t)b*ML + nn1) * (NH*DK) + h*DK + lane]      = a10;
    out[((size_t)b*ML + nn1) * (NH*DK) + h*DK + lane + 32] = a11;
}

// ---------------- launch ----------------
extern "C" void kernel_launch(void* const* d_in, const int* in_sizes, int n_in,
                              void* d_out, int out_size)
{
    const float* item    = (const float*)d_in[0];
    const float* intent  = (const float*)d_in[1];
    // d_in[2] mask: constant all-true by construction, unused.
    const int*   b_seq   = (const int*)d_in[3];
    const int*   b_seq2  = (const int*)d_in[4];
    const float* W_item  = (const float*)d_in[5];
    const float* W_intent= (const float*)d_in[6];
    float*       out     = (float*)d_out;

    zero_counts_kernel<<<1, 64>>>();
    build_groups_kernel<<<(BS*ML + BS*N2V + 255) / 256, 256>>>(b_seq, b_seq2);

    float *pq, *pk, *pv; int *prq, *prkv, *pcq, *pckv;
    cudaGetSymbolAddress((void**)&pq,   g_q);
    cudaGetSymbolAddress((void**)&pk,   g_k);
    cudaGetSymbolAddress((void**)&pv,   g_v);
    cudaGetSymbolAddress((void**)&prq,  g_rows_q);
    cudaGetSymbolAddress((void**)&prkv, g_rows_kv);
    cudaGetSymbolAddress((void**)&pcq,  g_cnt_q);
    cudaGetSymbolAddress((void**)&pckv, g_cnt_kv);

    int psmem = (PR_OFF + 64) * sizeof(float);   // 52,480 B
    cudaFuncSetAttribute(proj_gemm_kernel, cudaFuncAttributeMaxDynamicSharedMemorySize, psmem);
    proj_gemm_kernel<<<dim3(17*8, NB1, 6), 256, psmem>>>(
        item, intent, W_item, W_intent,
        prq, pcq, prkv, pckv, pq, pk, pv);

    int smem = (16*DK + 16*N2V + 32*KPAD) * sizeof(float);  // 106,752 B
    cudaFuncSetAttribute(attn_kernel, cudaFuncAttributeMaxDynamicSharedMemorySize, smem);
    attn_kernel<<<dim3(ML/16, NH, BS), 256, smem>>>(pq, pk, pv, out);

    (void)in_sizes; (void)n_in; (void)out_size;
}

// round 17
// speedup vs baseline: 1.0148x; 1.0148x over previous
#include <cuda_runtime.h>
#include <cstdint>

#define BS   2
#define NH   16
#define NB1  9
#define ML   1024
#define NI   64
#define N2V  1088
#define DM   1024
#define DK   64
#define TOPK 16
#define KPAD 258

typedef unsigned long long ull;

// ---------------- f32x2 packed helpers (each lane = independent IEEE fp32 op) ----
__device__ __forceinline__ ull pk2(float lo, float hi) {
    ull r; asm("mov.b64 %0,{%1,%2};" : "=l"(r) : "f"(lo), "f"(hi)); return r;
}
__device__ __forceinline__ float2 upk2(ull a) {
    float2 f; asm("mov.b64 {%0,%1},%2;" : "=f"(f.x), "=f"(f.y) : "l"(a)); return f;
}
__device__ __forceinline__ ull fma2(ull a, ull b, ull c) {
    ull d; asm("fma.rn.f32x2 %0,%1,%2,%3;" : "=l"(d) : "l"(a), "l"(b), "l"(c)); return d;
}
__device__ __forceinline__ ull add2(ull a, ull b) {
    ull d; asm("add.rn.f32x2 %0,%1,%2;" : "=l"(d) : "l"(a), "l"(b)); return d;
}
__device__ __forceinline__ ull neg2(ull a) { return a ^ 0x8000000080000000ULL; }

// packed Kahan fold: acc += part with compensation (exact match of scalar version)
__device__ __forceinline__ void kahan2(ull& acc, ull& cmp, ull part) {
    ull y  = add2(part, neg2(cmp));
    ull t2 = add2(acc, y);
    cmp = add2(add2(t2, neg2(acc)), neg2(y));
    acc = t2;
}

// order-preserving fp32 <-> u32 bijection (no NaNs in this data)
__device__ __forceinline__ unsigned xf(float v) {
    unsigned b = __float_as_uint(v);
    return (b & 0x80000000u) ? ~b : (b | 0x80000000u);
}
__device__ __forceinline__ float ixf(unsigned u) {
    unsigned b = (u & 0x80000000u) ? (u & 0x7fffffffu) : ~u;
    return __uint_as_float(b);
}

// ---------------- device scratch ----------------
__device__ float g_q[BS*NH*ML*DK];
__device__ float g_k[BS*NH*N2V*DK];
__device__ float g_v[BS*NH*N2V*DK];
__device__ int   g_rows_q[BS*NB1*ML];
__device__ int   g_rows_kv[BS*NB1*N2V];
__device__ int   g_cnt_q[BS*NB1];
__device__ int   g_cnt_kv[BS*NB1];

// ---------------- group building ----------------
__global__ void zero_counts_kernel() {
    int t = threadIdx.x;
    if (t < BS*NB1) { g_cnt_q[t] = 0; g_cnt_kv[t] = 0; }
}

__global__ void build_groups_kernel(const int* __restrict__ b_seq,
                                    const int* __restrict__ b_seq2) {
    int t = blockIdx.x * blockDim.x + threadIdx.x;
    if (t < BS*ML) {
        int b = t / ML;
        int B = b_seq[t];
        int pos = atomicAdd(&g_cnt_q[b*NB1 + B], 1);
        g_rows_q[(b*NB1 + B)*ML + pos] = t % ML;
    } else if (t < BS*ML + BS*N2V) {
        int u = t - BS*ML;
        int b = u / N2V;
        int B = b_seq2[u];
        int pos = atomicAdd(&g_cnt_kv[b*NB1 + B], 1);
        g_rows_kv[(b*NB1 + B)*N2V + pos] = u % N2V;
    }
}

// ---------------- cp.async helpers ----------------
__device__ __forceinline__ void cp_async16(uint32_t smem_addr, const void* gptr) {
    asm volatile("cp.async.ca.shared.global [%0], [%1], 16;\n"
                 :: "r"(smem_addr), "l"(gptr));
}
__device__ __forceinline__ void cp_async_commit() {
    asm volatile("cp.async.commit_group;\n");
}
__device__ __forceinline__ void cp_async_wait0() {
    asm volatile("cp.async.wait_group 0;\n");
}

// ---------------- merged grouped projection GEMM: 64-k super-chunks ---------
// Four sequential 16-k partial+Kahan folds per buffer (global chunk order
// 0,1,2,... preserved -> numerics bit-identical). A prefetch split in halves.
// Dynamic smem: B[2][64][136] + A[2][64][68] + rows[64] = 104,832 B/block.
#define PBF (64*136)
#define PAF (64*68)
#define PA_OFF (2*PBF)
#define PR_OFF (PA_OFF + 2*PAF)
__global__ __launch_bounds__(256, 2)
void proj_gemm_kernel(const float* __restrict__ item,
                      const float* __restrict__ intent,
                      const float* __restrict__ W_item,
                      const float* __restrict__ W_intent,
                      const int* __restrict__ rows_q, const int* __restrict__ cnt_q,
                      const int* __restrict__ rows_kv, const int* __restrict__ cnt_kv,
                      float* __restrict__ Oq, float* __restrict__ Ok, float* __restrict__ Ov)
{
    extern __shared__ __align__(16) float psm[];
    int*   rows_s = (int*)(psm + PR_OFF);

    int z     = blockIdx.z;
    int which = z >> 1;          // 0=q, 1=k, 2=v
    int b     = z & 1;
    int B     = blockIdx.y;
    int tm    = blockIdx.x % 17;
    int tn    = blockIdx.x / 17;         // 0..7

    const float* X;  const float* W;  const int* rl;  int cnt, Rin;
    float* O;
    if (which == 0) {
        cnt = cnt_q[b*NB1 + B];
        X = item;   W = W_item  + (size_t)B * (DM*DM);
        rl = rows_q  + (size_t)(b*NB1 + B) * ML;   Rin = ML;   O = Oq;
    } else {
        cnt = cnt_kv[b*NB1 + B];
        X = intent; W = W_intent + (size_t)(which-1) * (NB1*DM*DM) + (size_t)B * (DM*DM);
        rl = rows_kv + (size_t)(b*NB1 + B) * N2V;  Rin = N2V;
        O = (which == 1) ? Ok : Ov;
    }
    int Rout = (which == 0) ? ML : N2V;

    int m0 = tm * 64;
    if (m0 >= cnt) return;
    int n0 = tn * 128;

    int t = threadIdx.x;
    if (t < 64) rows_s[t] = (m0 + t < cnt) ? rl[m0 + t] : -1;
    __syncthreads();

    int ai = t >> 2;
    int akq = (t & 3) * 4;
    int aRow = rows_s[ai];
    const float* aSrc = (aRow >= 0) ? &X[((size_t)b * Rin + aRow) * DM + akq] : nullptr;

    int ty = t >> 4;
    int tx = t & 15;

    ull acc2[4][4], cmp2[4][4];
#pragma unroll
    for (int i = 0; i < 4; i++)
#pragma unroll
        for (int j = 0; j < 4; j++) { acc2[i][j] = 0ULL; cmp2[i][j] = 0ULL; }

    uint32_t bBase = (uint32_t)__cvta_generic_to_shared(psm);
    // 8 cp.async segments per thread cover 64x128 B floats
    int kkS[8], cS[8];
#pragma unroll
    for (int s = 0; s < 8; s++) {
        int idx = t + 256*s;
        kkS[s] = idx >> 5;          // 0..63
        cS[s]  = (idx & 31) * 4;    // 0..124
    }

    // ---- prologue: super-chunk 0 ----
    {
        uint32_t bb = bBase;
#pragma unroll
        for (int s = 0; s < 8; s++)
            cp_async16(bb + (uint32_t)(kkS[s]*136 + cS[s])*4, &W[(size_t)kkS[s] * DM + n0 + cS[s]]);
        cp_async_commit();
        float* A0 = psm + PA_OFF;
#pragma unroll
        for (int hh = 0; hh < 4; hh++) {
            float4 av = make_float4(0.f,0.f,0.f,0.f);
            if (aSrc) av = *(const float4*)(aSrc + hh*16);
            A0[(akq+0 + hh*16)*68 + ai] = av.x; A0[(akq+1 + hh*16)*68 + ai] = av.y;
            A0[(akq+2 + hh*16)*68 + ai] = av.z; A0[(akq+3 + hh*16)*68 + ai] = av.w;
        }
        cp_async_wait0();
        __syncthreads();
    }

    const int NSC = DM / 64;   // 16 super-chunks
    for (int i = 0; i < NSC; i++) {
        int cur = i & 1, nxt = cur ^ 1;
        bool pre = (i + 1 < NSC);
        int kp1 = (i + 1) * 64;
        float4 av0, av1;
        if (pre) {
            uint32_t bb = bBase + (uint32_t)(nxt * PBF) * 4;
#pragma unroll
            for (int s = 0; s < 8; s++)
                cp_async16(bb + (uint32_t)(kkS[s]*136 + cS[s])*4, &W[(size_t)(kp1 + kkS[s]) * DM + n0 + cS[s]]);
            cp_async_commit();
            av0 = make_float4(0.f,0.f,0.f,0.f); av1 = av0;
            if (aSrc) { av0 = *(const float4*)(aSrc + kp1); av1 = *(const float4*)(aSrc + kp1 + 16); }
        }

        const float* Bc = psm + cur * PBF;
        const float* Ac = psm + PA_OFF + cur * PAF;
        float* An = psm + PA_OFF + nxt * PAF;

        // ---- kh = 0,1 (k 0..31 of this super-chunk, global order preserved) ----
#pragma unroll
        for (int kh = 0; kh < 2; kh++) {
            ull part2[4][4];
#pragma unroll
            for (int ii = 0; ii < 4; ii++)
#pragma unroll
                for (int j = 0; j < 4; j++) part2[ii][j] = 0ULL;
#pragma unroll
            for (int kq = 0; kq < 16; kq++) {
                int kk = kh*16 + kq;
                float4 a4 = *(const float4*)&Ac[kk*68 + ty*4];
                const ull* bpa = (const ull*)&Bc[kk*136 + tx*4];
                const ull* bpb = (const ull*)&Bc[kk*136 + 64 + tx*4];
                ull b2[4] = { bpa[0], bpa[1], bpb[0], bpb[1] };
                ull a2[4] = { pk2(a4.x, a4.x), pk2(a4.y, a4.y),
                              pk2(a4.z, a4.z), pk2(a4.w, a4.w) };
#pragma unroll
                for (int ii = 0; ii < 4; ii++)
#pragma unroll
                    for (int j = 0; j < 4; j++)
                        part2[ii][j] = fma2(a2[ii], b2[j], part2[ii][j]);
            }
#pragma unroll
            for (int ii = 0; ii < 4; ii++)
#pragma unroll
                for (int j = 0; j < 4; j++)
                    kahan2(acc2[ii][j], cmp2[ii][j], part2[ii][j]);
        }

        float4 av2, av3;
        if (pre) {
            // store first A half, fetch second half
            An[(akq+0)*68 + ai]  = av0.x; An[(akq+1)*68 + ai]  = av0.y;
            An[(akq+2)*68 + ai]  = av0.z; An[(akq+3)*68 + ai]  = av0.w;
            An[(akq+16)*68 + ai] = av1.x; An[(akq+17)*68 + ai] = av1.y;
            An[(akq+18)*68 + ai] = av1.z; An[(akq+19)*68 + ai] = av1.w;
            av2 = make_float4(0.f,0.f,0.f,0.f); av3 = av2;
            if (aSrc) { av2 = *(const float4*)(aSrc + kp1 + 32); av3 = *(const float4*)(aSrc + kp1 + 48); }
        }

        // ---- kh = 2,3 ----
#pragma unroll
        for (int kh = 2; kh < 4; kh++) {
            ull part2[4][4];
#pragma unroll
            for (int ii = 0; ii < 4; ii++)
#pragma unroll
                for (int j = 0; j < 4; j++) part2[ii][j] = 0ULL;
#pragma unroll
            for (int kq = 0; kq < 16; kq++) {
                int kk = kh*16 + kq;
                float4 a4 = *(const float4*)&Ac[kk*68 + ty*4];
                const ull* bpa = (const ull*)&Bc[kk*136 + tx*4];
                const ull* bpb = (const ull*)&Bc[kk*136 + 64 + tx*4];
                ull b2[4] = { bpa[0], bpa[1], bpb[0], bpb[1] };
                ull a2[4] = { pk2(a4.x, a4.x), pk2(a4.y, a4.y),
                              pk2(a4.z, a4.z), pk2(a4.w, a4.w) };
#pragma unroll
                for (int ii = 0; ii < 4; ii++)
#pragma unroll
                    for (int j = 0; j < 4; j++)
                        part2[ii][j] = fma2(a2[ii], b2[j], part2[ii][j]);
            }
#pragma unroll
            for (int ii = 0; ii < 4; ii++)
#pragma unroll
                for (int j = 0; j < 4; j++)
                    kahan2(acc2[ii][j], cmp2[ii][j], part2[ii][j]);
        }

        if (pre) {
            An[(akq+32)*68 + ai] = av2.x; An[(akq+33)*68 + ai] = av2.y;
            An[(akq+34)*68 + ai] = av2.z; An[(akq+35)*68 + ai] = av2.w;
            An[(akq+48)*68 + ai] = av3.x; An[(akq+49)*68 + ai] = av3.y;
            An[(akq+50)*68 + ai] = av3.z; An[(akq+51)*68 + ai] = av3.w;
            cp_async_wait0();
        }
        __syncthreads();
    }

    // epilogue
#pragma unroll
    for (int i = 0; i < 4; i++) {
        int n = rows_s[ty*4 + i];
        if (n < 0) continue;
#pragma unroll
        for (int jp = 0; jp < 4; jp++) {
            float2 v = upk2(acc2[i][jp]);
            int cbase = n0 + ((jp < 2) ? (tx*4 + jp*2) : (64 + tx*4 + (jp-2)*2));
#pragma unroll
            for (int l = 0; l < 2; l++) {
                int col = cbase + l;
                int h   = col >> 6;
                int kd  = col & 63;
                O[(((size_t)b*NH + h) * Rout + n) * DK + kd] = (l == 0) ? v.x : v.y;
            }
        }
    }
}

// ---------------- fused attention (R16 exact): REDUX selection ---------------
__global__ __launch_bounds__(256, 2)
void attn_kernel(const float* __restrict__ q, const float* __restrict__ kmat,
                 const float* __restrict__ vmat, float* __restrict__ out)
{
    extern __shared__ __align__(16) float sm[];
    float* q_s = sm;                       // 16*64   = 1024
    float* sc  = sm + 16*DK;               // 16*1088 = 17408
    float* k_s = sc + 16*N2V;              // 32*KPAD = 8256

    int b  = blockIdx.z;
    int h  = blockIdx.y;
    int n0 = blockIdx.x * 16;
    int t  = threadIdx.x;

    {
        const float4* qb = (const float4*)(q + (((size_t)(b*NH + h)) * ML + n0) * DK);
        ((float4*)q_s)[t] = qb[t];
    }

    const float* kb = kmat + ((size_t)(b*NH + h)) * N2V * DK;

    int tm = t & 63;
    int tr = t >> 6;
    int mlb = t >> 3;
    int c4  = (t & 7) * 4;

    for (int mc = 0; mc < N2V; mc += 256) {
        ull acc2[4][2], cmp2[4][2];
#pragma unroll
        for (int i = 0; i < 4; i++)
#pragma unroll
            for (int j = 0; j < 2; j++) { acc2[i][j] = 0ULL; cmp2[i][j] = 0ULL; }

#pragma unroll
        for (int h2 = 0; h2 < 2; h2++) {
            __syncthreads();
#pragma unroll
            for (int r = 0; r < 8; r++) {
                int ml = mlb + r * 32;
                int m  = mc + ml;
                float4 vv = make_float4(0.f, 0.f, 0.f, 0.f);
                if (m < N2V) vv = *(const float4*)(kb + (size_t)m * DK + h2*32 + c4);
                k_s[(c4+0)*KPAD + ml] = vv.x; k_s[(c4+1)*KPAD + ml] = vv.y;
                k_s[(c4+2)*KPAD + ml] = vv.z; k_s[(c4+3)*KPAD + ml] = vv.w;
            }
            __syncthreads();

#pragma unroll
            for (int kh = 0; kh < 2; kh++) {
                int kc = 2*h2 + kh;
                ull part2[4][2];
#pragma unroll
                for (int i = 0; i < 4; i++)
#pragma unroll
                    for (int j = 0; j < 2; j++) part2[i][j] = 0ULL;

#pragma unroll
                for (int kq = 0; kq < 16; kq++) {
                    int kkl = kh*16 + kq;
                    const float* kr = k_s + kkl*KPAD;
                    ull k2a = *(const ull*)(kr + 2*tm);
                    ull k2b = *(const ull*)(kr + 128 + 2*tm);
#pragma unroll
                    for (int rr = 0; rr < 4; rr++) {
                        float qv = q_s[(tr*4 + rr) * DK + kc*16 + kq];
                        ull q2 = pk2(qv, qv);
                        part2[rr][0] = fma2(q2, k2a, part2[rr][0]);
                        part2[rr][1] = fma2(q2, k2b, part2[rr][1]);
                    }
                }
#pragma unroll
                for (int i = 0; i < 4; i++)
#pragma unroll
                    for (int j = 0; j < 2; j++)
                        kahan2(acc2[i][j], cmp2[i][j], part2[i][j]);
            }
        }

#pragma unroll
        for (int p = 0; p < 2; p++) {
            int mbase = mc + p*128 + 2*tm;
            if (mbase >= N2V) continue;
#pragma unroll
            for (int rr = 0; rr < 4; rr++) {
                int row = tr*4 + rr;
                float2 s2 = upk2(acc2[rr][p]);
                s2.x *= 0.125f; s2.y *= 0.125f;
                *(float2*)(sc + row*N2V + mbase) = s2;
            }
        }
    }
    __syncthreads();

    int warp = t >> 5, lane = t & 31;
    const float* vb = vmat + ((size_t)(b*NH + h)) * N2V * DK;
    const size_t XSZ = (size_t)BS * ML * NH * DK;

    float* pbuf = k_s;
    int*   ibuf = (int*)(k_s + 16*64);

    int row0 = warp * 2, row1 = row0 + 1;
    int nn0 = n0 + row0, nn1 = n0 + row1;
    float* sr0 = sc + row0 * N2V;
    float* sr1 = sc + row1 * N2V;

    float M0 = -3.4e38f, M1 = -3.4e38f;
#pragma unroll
    for (int j = 0; j < 34; j++) {
        M0 = fmaxf(M0, sr0[lane + 32*j]);
        M1 = fmaxf(M1, sr1[lane + 32*j]);
    }
    M0 = ixf(__reduce_max_sync(0xffffffffu, xf(M0)));
    M1 = ixf(__reduce_max_sync(0xffffffffu, xf(M1)));
    float Z0 = 0.f, Z1 = 0.f;
#pragma unroll
    for (int j = 0; j < 34; j++) {
        Z0 += __expf(sr0[lane + 32*j] - M0);
        Z1 += __expf(sr1[lane + 32*j] - M1);
    }
#pragma unroll
    for (int o = 16; o > 0; o >>= 1) {
        Z0 += __shfl_xor_sync(0xffffffffu, Z0, o);
        Z1 += __shfl_xor_sync(0xffffffffu, Z1, o);
    }
    float invZ0 = 1.0f / Z0, invZ1 = 1.0f / Z1;

    // --- selection, segment A: dual per-lane (top1, top2), REDUX argmax ---
    {
        float lbv0 = -3.4e38f, lv20 = -3.4e38f; int lbi0 = lane, li20 = lane; bool need0 = false;
        float lbv1 = -3.4e38f, lv21 = -3.4e38f; int lbi1 = lane, li21 = lane; bool need1 = false;
#pragma unroll
        for (int j = 0; j < 32; j++) {
            int idx = lane + 32*j;
            float s0 = sr0[idx], s1 = sr1[idx];
            if (s0 > lbv0)      { lv20 = lbv0; li20 = lbi0; lbv0 = s0; lbi0 = idx; }
            else if (s0 > lv20) { lv20 = s0;  li20 = idx; }
            if (s1 > lbv1)      { lv21 = lbv1; li21 = lbi1; lbv1 = s1; lbi1 = idx; }
            else if (s1 > lv21) { lv21 = s1;  li21 = idx; }
        }
        unsigned lu0 = xf(lbv0), lu1 = xf(lbv1);
        for (int it = 0; it < TOPK; it++) {
            unsigned mu0 = __reduce_max_sync(0xffffffffu, lu0);
            unsigned mu1 = __reduce_max_sync(0xffffffffu, lu1);
            int bi0 = __reduce_min_sync(0xffffffffu, (lu0 == mu0) ? lbi0 : 0x7fffffff);
            int bi1 = __reduce_min_sync(0xffffffffu, (lu1 == mu1) ? lbi1 : 0x7fffffff);
            float bv0 = ixf(mu0), bv1 = ixf(mu1);
            if ((bi0 & 31) == lane) {
                sr0[bi0] = -3.4e38f;
                if (need0) {
                    lbv0 = -3.4e38f; lv20 = -3.4e38f; lbi0 = lane; li20 = lane;
#pragma unroll
                    for (int j = 0; j < 32; j++) {
                        int idx = lane + 32*j;
                        float s = sr0[idx];
                        if (s > lbv0)      { lv20 = lbv0; li20 = lbi0; lbv0 = s; lbi0 = idx; }
                        else if (s > lv20) { lv20 = s;  li20 = idx; }
                    }
                    need0 = false;
                } else { lbv0 = lv20; lbi0 = li20; need0 = true; }
                lu0 = xf(lbv0);
            }
            if ((bi1 & 31) == lane) {
                sr1[bi1] = -3.4e38f;
                if (need1) {
                    lbv1 = -3.4e38f; lv21 = -3.4e38f; lbi1 = lane; li21 = lane;
#pragma unroll
                    for (int j = 0; j < 32; j++) {
                        int idx = lane + 32*j;
                        float s = sr1[idx];
                        if (s > lbv1)      { lv21 = lbv1; li21 = lbi1; lbv1 = s; lbi1 = idx; }
                        else if (s > lv21) { lv21 = s;  li21 = idx; }
                    }
                    need1 = false;
                } else { lbv1 = lv21; lbi1 = li21; need1 = true; }
                lu1 = xf(lbv1);
            }
            __syncwarp();
            if (lane == 0) {
                pbuf[row0*64 + it] = bv0; ibuf[row0*64 + it] = bi0;
                pbuf[row1*64 + it] = bv1; ibuf[row1*64 + it] = bi1;
                if (h == 0 && it == 0) {
                    out[XSZ + (size_t)b*ML + nn0] = (float)bi0;
                    out[XSZ + (size_t)b*ML + nn1] = (float)bi1;
                }
            }
        }
    }

    // --- selection, segment B: dual, 2 elems/lane, REDUX argmax ---
    {
        float lbv0, lv20, lbv1, lv21;
        int   lbi0, li20, lbi1, li21;
        {
            float s0 = sr0[ML + lane], s1 = sr0[ML + lane + 32];
            if (s0 >= s1) { lbv0 = s0; lbi0 = ML + lane;      lv20 = s1; li20 = ML + lane + 32; }
            else          { lbv0 = s1; lbi0 = ML + lane + 32; lv20 = s0; li20 = ML + lane; }
        }
        {
            float s0 = sr1[ML + lane], s1 = sr1[ML + lane + 32];
            if (s0 >= s1) { lbv1 = s0; lbi1 = ML + lane;      lv21 = s1; li21 = ML + lane + 32; }
            else          { lbv1 = s1; lbi1 = ML + lane + 32; lv21 = s0; li21 = ML + lane; }
        }
        unsigned lu0 = xf(lbv0), lu1 = xf(lbv1);
        for (int it = 0; it < TOPK; it++) {
            unsigned mu0 = __reduce_max_sync(0xffffffffu, lu0);
            unsigned mu1 = __reduce_max_sync(0xffffffffu, lu1);
            int bi0 = __reduce_min_sync(0xffffffffu, (lu0 == mu0) ? lbi0 : 0x7fffffff);
            int bi1 = __reduce_min_sync(0xffffffffu, (lu1 == mu1) ? lbi1 : 0x7fffffff);
            float bv0 = ixf(mu0), bv1 = ixf(mu1);
            if ((bi0 & 31) == lane) { lbv0 = lv20; lbi0 = li20; lv20 = -3.4e38f; lu0 = xf(lbv0); }
            if ((bi1 & 31) == lane) { lbv1 = lv21; lbi1 = li21; lv21 = -3.4e38f; lu1 = xf(lbv1); }
            __syncwarp();
            if (lane == 0) {
                pbuf[row0*64 + 16 + it] = bv0; ibuf[row0*64 + 16 + it] = bi0;
                pbuf[row1*64 + 16 + it] = bv1; ibuf[row1*64 + 16 + it] = bi1;
                if (h == 0 && it == 0) {
                    out[XSZ + (size_t)BS*ML + (size_t)b*ML + nn0] = (float)(bi0 - ML);
                    out[XSZ + (size_t)BS*ML + (size_t)b*ML + nn1] = (float)(bi1 - ML);
                }
            }
        }
    }
    __syncwarp();

    // --- PV, both rows interleaved ---
    float a00 = 0.f, a01 = 0.f, a10 = 0.f, a11 = 0.f;
#pragma unroll 4
    for (int it = 0; it < 32; it++) {
        float bv0 = pbuf[row0*64 + it]; int g0 = ibuf[row0*64 + it];
        float bv1 = pbuf[row1*64 + it]; int g1 = ibuf[row1*64 + it];
        float p0 = __expf(bv0 - M0) * invZ0;
        float p1 = __expf(bv1 - M1) * invZ1;
        const float* v0 = vb + (size_t)g0 * DK;
        const float* v1 = vb + (size_t)g1 * DK;
        a00 += p0 * v0[lane];  a01 += p0 * v0[lane + 32];
        a10 += p1 * v1[lane];  a11 += p1 * v1[lane + 32];
    }

    out[((size_t)b*ML + nn0) * (NH*DK) + h*DK + lane]      = a00;
    out[((size_t)b*ML + nn0) * (NH*DK) + h*DK + lane + 32] = a01;
    out[((size_t)b*ML + nn1) * (NH*DK) + h*DK + lane]      = a10;
    out[((size_t)b*ML + nn1) * (NH*DK) + h*DK + lane + 32] = a11;
}

// ---------------- launch ----------------
extern "C" void kernel_launch(void* const* d_in, const int* in_sizes, int n_in,
                              void* d_out, int out_size)
{
    const float* item    = (const float*)d_in[0];
    const float* intent  = (const float*)d_in[1];
    // d_in[2] mask: constant all-true by construction, unused.
    const int*   b_seq   = (const int*)d_in[3];
    const int*   b_seq2  = (const int*)d_in[4];
    const float* W_item  = (const float*)d_in[5];
    const float* W_intent= (const float*)d_in[6];
    float*       out     = (float*)d_out;

    zero_counts_kernel<<<1, 64>>>();
    build_groups_kernel<<<(BS*ML + BS*N2V + 255) / 256, 256>>>(b_seq, b_seq2);

    float *pq, *pk, *pv; int *prq, *prkv, *pcq, *pckv;
    cudaGetSymbolAddress((void**)&pq,   g_q);
    cudaGetSymbolAddress((void**)&pk,   g_k);
    cudaGetSymbolAddress((void**)&pv,   g_v);
    cudaGetSymbolAddress((void**)&prq,  g_rows_q);
    cudaGetSymbolAddress((void**)&prkv, g_rows_kv);
    cudaGetSymbolAddress((void**)&pcq,  g_cnt_q);
    cudaGetSymbolAddress((void**)&pckv, g_cnt_kv);

    int psmem = (PR_OFF + 64) * sizeof(float);   // 104,832 B
    cudaFuncSetAttribute(proj_gemm_kernel, cudaFuncAttributeMaxDynamicSharedMemorySize, psmem);
    proj_gemm_kernel<<<dim3(17*8, NB1, 6), 256, psmem>>>(
        item, intent, W_item, W_intent,
        prq, pcq, prkv, pckv, pq, pk, pv);

    int smem = (16*DK + 16*N2V + 32*KPAD) * sizeof(float);  // 106,752 B
    cudaFuncSetAttribute(attn_kernel, cudaFuncAttributeMaxDynamicSharedMemorySize, smem);
    attn_kernel<<<dim3(ML/16, NH, BS), 256, smem>>>(pq, pk, pv, out);

    (void)in_sizes; (void)n_in; (void)out_size;
}